// round 2
// baseline (speedup 1.0000x reference)
#include <cuda_runtime.h>
#include <cstdint>

// ---------------------------------------------------------------------------
// Scratch (allocation-free rule: __device__ globals)
// ---------------------------------------------------------------------------
__device__ float g_buf1[32u * 64u * 128u * 128u];   // conv1 out (134 MB)
__device__ float g_buf2[32u * 128u * 64u * 64u];    // conv2 out (67 MB)
__device__ float g_buf3[32u * 256u * 32u * 32u];    // conv3 out (33.5 MB)
__device__ float g_zf[8192u * 256u];                // conv4 out, (N*H*W, C) row-major
__device__ float g_cbnorm[8192];                    // ||codebook_k||^2
__device__ unsigned long long g_min[8192];          // packed (dist_key<<32 | idx)

// ---------------------------------------------------------------------------
// Conv2d k=4 s=2 p=1 + ReLU, NCHW in / NCHW out (or zf layout for last layer)
// Each thread: one output pixel, 4 consecutive output channels.
// Weights loaded per-ci as float4 rows (LDG.128, warp-uniform -> L1 broadcast).
// ---------------------------------------------------------------------------
template <int CI, int CO, int HI, int WI, bool ZF_OUT>
__global__ void conv4x4s2_relu(const float* __restrict__ in,
                               const float* __restrict__ w,
                               const float* __restrict__ bias,
                               float* __restrict__ out, int N) {
    constexpr int HO = HI / 2, WO = WI / 2;
    constexpr int COG = CO / 4;
    int idx = blockIdx.x * blockDim.x + threadIdx.x;
    int total = N * COG * HO * WO;
    if (idx >= total) return;

    int wo = idx % WO;  int t = idx / WO;
    int ho = t % HO;    t /= HO;
    int cog = t % COG;  int n = t / COG;
    int co = cog * 4;

    float a0 = bias[co + 0], a1 = bias[co + 1], a2 = bias[co + 2], a3 = bias[co + 3];

    int hi0 = 2 * ho - 1;
    int wi0 = 2 * wo - 1;
    const float* wbase = w + (long)co * CI * 16;

    for (int ci = 0; ci < CI; ci++) {
        const float* ip = in + ((long)n * CI + ci) * HI * WI;
        const float* wp = wbase + ci * 16;

        // weights for this ci: 4 output channels x 4 kh-rows, each row a float4
        float4 wr0[4], wr1[4], wr2[4], wr3[4];
#pragma unroll
        for (int kh = 0; kh < 4; kh++) {
            wr0[kh] = __ldg(reinterpret_cast<const float4*>(wp + 0 * CI * 16 + kh * 4));
            wr1[kh] = __ldg(reinterpret_cast<const float4*>(wp + 1 * CI * 16 + kh * 4));
            wr2[kh] = __ldg(reinterpret_cast<const float4*>(wp + 2 * CI * 16 + kh * 4));
            wr3[kh] = __ldg(reinterpret_cast<const float4*>(wp + 3 * CI * 16 + kh * 4));
        }

#pragma unroll
        for (int kh = 0; kh < 4; kh++) {
            int hi = hi0 + kh;
            if ((unsigned)hi >= (unsigned)HI) continue;
            const float* iprow = ip + (long)hi * WI;

            float v;
            int wi;
            wi = wi0 + 0;
            if ((unsigned)wi < (unsigned)WI) {
                v = __ldg(iprow + wi);
                a0 = fmaf(v, wr0[kh].x, a0); a1 = fmaf(v, wr1[kh].x, a1);
                a2 = fmaf(v, wr2[kh].x, a2); a3 = fmaf(v, wr3[kh].x, a3);
            }
            wi = wi0 + 1;
            if ((unsigned)wi < (unsigned)WI) {
                v = __ldg(iprow + wi);
                a0 = fmaf(v, wr0[kh].y, a0); a1 = fmaf(v, wr1[kh].y, a1);
                a2 = fmaf(v, wr2[kh].y, a2); a3 = fmaf(v, wr3[kh].y, a3);
            }
            wi = wi0 + 2;
            if ((unsigned)wi < (unsigned)WI) {
                v = __ldg(iprow + wi);
                a0 = fmaf(v, wr0[kh].z, a0); a1 = fmaf(v, wr1[kh].z, a1);
                a2 = fmaf(v, wr2[kh].z, a2); a3 = fmaf(v, wr3[kh].z, a3);
            }
            wi = wi0 + 3;
            if ((unsigned)wi < (unsigned)WI) {
                v = __ldg(iprow + wi);
                a0 = fmaf(v, wr0[kh].w, a0); a1 = fmaf(v, wr1[kh].w, a1);
                a2 = fmaf(v, wr2[kh].w, a2); a3 = fmaf(v, wr3[kh].w, a3);
            }
        }
    }
    a0 = fmaxf(a0, 0.f); a1 = fmaxf(a1, 0.f); a2 = fmaxf(a2, 0.f); a3 = fmaxf(a3, 0.f);

    if (ZF_OUT) {
        // (row = n*HO*WO + p, col = co..co+3), row-major with stride CO
        int p = ho * WO + wo;
        float* op = out + ((long)n * HO * WO + p) * CO + co;
        op[0] = a0; op[1] = a1; op[2] = a2; op[3] = a3;
    } else {
        long base = (((long)n * CO + co) * HO + ho) * WO + wo;
        const long cs = (long)HO * WO;
        out[base + 0 * cs] = a0;
        out[base + 1 * cs] = a1;
        out[base + 2 * cs] = a2;
        out[base + 3 * cs] = a3;
    }
}

// ---------------------------------------------------------------------------
// Codebook row norms
// ---------------------------------------------------------------------------
__global__ void cbnorm_kernel(const float* __restrict__ cb) {
    int code = blockIdx.x * blockDim.x + threadIdx.x;   // 8192 threads
    const float4* p = reinterpret_cast<const float4*>(cb + (long)code * 256);
    float s = 0.f;
#pragma unroll 8
    for (int k = 0; k < 64; k++) {
        float4 v = __ldg(p + k);
        s += v.x * v.x + v.y * v.y + v.z * v.z + v.w * v.w;
    }
    g_cbnorm[code] = s;
}

__global__ void initmin_kernel() {
    int i = blockIdx.x * blockDim.x + threadIdx.x;
    g_min[i] = ~0ULL;
}

// ---------------------------------------------------------------------------
// Fused VQ GEMM + argmin:
//   S = zf (8192x256) @ cb^T (256x8192), d = ||c||^2 - 2 S  (row norm dropped)
//   per-row argmin reduced via packed-u64 atomicMin (monotone float key).
// Tile 64x64, K-step 16, 256 threads, 4x4 register tiles.
// ---------------------------------------------------------------------------
__global__ void vq_gemm_argmin(const float* __restrict__ cb) {
    __shared__ float As[16][65];
    __shared__ float Bs[16][65];
    __shared__ unsigned long long smin[64];

    int tid = threadIdx.x;
    int rowBase = blockIdx.y * 64;
    int colBase = blockIdx.x * 64;
    int ty = tid / 16, tx = tid % 16;

    int lr = tid >> 2;          // 0..63 (tile row for loads)
    int lk = (tid & 3) * 4;     // 0,4,8,12 (k offset for float4 load)

    if (tid < 64) smin[tid] = ~0ULL;

    float acc[4][4];
#pragma unroll
    for (int i = 0; i < 4; i++)
#pragma unroll
        for (int j = 0; j < 4; j++) acc[i][j] = 0.f;

    for (int k0 = 0; k0 < 256; k0 += 16) {
        float4 av = *reinterpret_cast<const float4*>(&g_zf[(long)(rowBase + lr) * 256 + k0 + lk]);
        float4 bv = __ldg(reinterpret_cast<const float4*>(&cb[(long)(colBase + lr) * 256 + k0 + lk]));
        __syncthreads();
        As[lk + 0][lr] = av.x; As[lk + 1][lr] = av.y; As[lk + 2][lr] = av.z; As[lk + 3][lr] = av.w;
        Bs[lk + 0][lr] = bv.x; Bs[lk + 1][lr] = bv.y; Bs[lk + 2][lr] = bv.z; Bs[lk + 3][lr] = bv.w;
        __syncthreads();
#pragma unroll
        for (int kk = 0; kk < 16; kk++) {
            float a[4], b[4];
#pragma unroll
            for (int i = 0; i < 4; i++) a[i] = As[kk][ty * 4 + i];
#pragma unroll
            for (int j = 0; j < 4; j++) b[j] = Bs[kk][tx * 4 + j];
#pragma unroll
            for (int i = 0; i < 4; i++)
#pragma unroll
                for (int j = 0; j < 4; j++)
                    acc[i][j] = fmaf(a[i], b[j], acc[i][j]);
        }
    }

#pragma unroll
    for (int i = 0; i < 4; i++) {
        float bestd = __int_as_float(0x7f800000);  // +inf
        int bestc = 0;
#pragma unroll
        for (int j = 0; j < 4; j++) {
            int col = colBase + tx * 4 + j;
            float d = g_cbnorm[col] - 2.f * acc[i][j];
            if (d < bestd) { bestd = d; bestc = col; }
        }
        unsigned ud = __float_as_uint(bestd);
        ud ^= (ud & 0x80000000u) ? 0xFFFFFFFFu : 0x80000000u;  // monotone key
        unsigned long long key = ((unsigned long long)ud << 32) | (unsigned)bestc;
        atomicMin(&smin[ty * 4 + i], key);
    }
    __syncthreads();
    if (tid < 64) atomicMin(&g_min[rowBase + tid], smin[tid]);
}

// ---------------------------------------------------------------------------
// Gather codebook rows into z_q (NCHW) + write idx.
// One block per row (spatial position), 256 threads = channels.
// ---------------------------------------------------------------------------
__global__ void gather_kernel(const float* __restrict__ cb,
                              float* __restrict__ out,
                              int write_zq, int write_idx, long idx_off) {
    int row = blockIdx.x;                 // 0..8191  (= n*256 + h*16 + w)
    int c = threadIdx.x;                  // 0..255
    unsigned idx = (unsigned)(g_min[row] & 0xFFFFFFFFu);
    if (write_zq) {
        float v = __ldg(cb + (long)idx * 256 + c);
        int n = row >> 8;
        int p = row & 255;
        out[(long)n * 65536 + (long)c * 256 + p] = v;   // z_q[n][c][h][w]
    }
    if (write_idx && c == 0) {
        out[idx_off + row] = (float)idx;
    }
}

// ---------------------------------------------------------------------------
// Launch
// ---------------------------------------------------------------------------
extern "C" void kernel_launch(void* const* d_in, const int* in_sizes, int n_in,
                              void* d_out, int out_size) {
    const float* x  = (const float*)d_in[0];
    const float* w1 = (const float*)d_in[1];
    const float* b1 = (const float*)d_in[2];
    const float* w2 = (const float*)d_in[3];
    const float* b2 = (const float*)d_in[4];
    const float* w3 = (const float*)d_in[5];
    const float* b3 = (const float*)d_in[6];
    const float* w4 = (const float*)d_in[7];
    const float* b4 = (const float*)d_in[8];
    const float* cb = (const float*)d_in[9];
    float* out = (float*)d_out;

    float* buf1; cudaGetSymbolAddress((void**)&buf1, g_buf1);
    float* buf2; cudaGetSymbolAddress((void**)&buf2, g_buf2);
    float* buf3; cudaGetSymbolAddress((void**)&buf3, g_buf3);
    float* zf;   cudaGetSymbolAddress((void**)&zf,   g_zf);

    const int N = 32;

    // conv chain
    conv4x4s2_relu<3,   64, 256, 256, false><<<(N*16*128*128)/256, 256>>>(x,    w1, b1, buf1, N);
    conv4x4s2_relu<64, 128, 128, 128, false><<<(N*32*64*64)/256,   256>>>(buf1, w2, b2, buf2, N);
    conv4x4s2_relu<128,256,  64,  64, false><<<(N*64*32*32)/256,   256>>>(buf2, w3, b3, buf3, N);
    conv4x4s2_relu<256,256,  32,  32, true ><<<(N*64*16*16)/256,   256>>>(buf3, w4, b4, zf,   N);

    // VQ
    cbnorm_kernel<<<32, 256>>>(cb);
    initmin_kernel<<<32, 256>>>();
    vq_gemm_argmin<<<dim3(128, 128), 256>>>(cb);

    // output layout: [z_q (2,097,152 floats)] [idx (8,192, cast to float)]
    const long ZQ = 2097152;
    int write_zq = 0, write_idx = 0; long idx_off = 0;
    if (out_size >= (int)(ZQ + 8192)) { write_zq = 1; write_idx = 1; idx_off = ZQ; }
    else if (out_size >= (int)ZQ)     { write_zq = 1; }
    else                              { write_idx = 1; idx_off = 0; }

    gather_kernel<<<8192, 256>>>(cb, out, write_zq, write_idx, idx_off);
}

// round 3
// speedup vs baseline: 2.7124x; 2.7124x over previous
#include <cuda_runtime.h>
#include <cstdint>

// ---------------------------------------------------------------------------
// Scratch (__device__ globals; no allocation allowed)
// ---------------------------------------------------------------------------
__device__ float g_a1[32u * 128u * 128u * 64u];   // conv1 out NHWC (33.5M)
__device__ float g_a2[32u * 64u * 64u * 128u];    // conv2 out NHWC (16.8M)
__device__ float g_a3[32u * 32u * 32u * 256u];    // conv3 out NHWC (8.4M)
__device__ float g_zf[8192u * 256u];              // conv4 out NHWC == zf
__device__ float g_wt2[16u * 64u * 128u];         // w2 transposed [tap][ci][co]
__device__ float g_wt3[16u * 128u * 256u];
__device__ float g_wt4[16u * 256u * 256u];
__device__ float g_cbnorm[8192];
__device__ unsigned long long g_min[8192];

// ---------------------------------------------------------------------------
// Weight transpose: w[co][ci][kh][kw] -> wT[(t*CI+ci)*CO + co], t = kh*4+kw
// ---------------------------------------------------------------------------
__global__ void wtrans_kernel(const float* __restrict__ w, float* __restrict__ wT,
                              int CI, int CO) {
    int id = blockIdx.x * 256 + threadIdx.x;
    int tot = CO * CI * 16;
    if (id >= tot) return;
    int co = id % CO;
    int r = id / CO;            // r = t*CI + ci
    int ci = r % CI;
    int t = r / CI;
    wT[id] = w[(co * CI + ci) * 16 + t];
}

// ---------------------------------------------------------------------------
// Conv1: CI=3, k=4 s=2 p=1 + bias + ReLU.  x NCHW (32,3,256,256) -> NHWC out.
// One thread per output pixel, all 64 output channels. Weights in smem.
// ---------------------------------------------------------------------------
__global__ __launch_bounds__(256) void conv1_nhwc(const float* __restrict__ x,
                                                  const float* __restrict__ w,
                                                  const float* __restrict__ b,
                                                  float* __restrict__ out) {
    __shared__ __align__(16) float ws[48][64];   // [ci*16 + kh*4+kw][co]
    __shared__ float sb[64];
    int tid = threadIdx.x;
    for (int i = tid; i < 3072; i += 256) {
        int tap = i >> 6, co = i & 63;
        ws[tap][co] = w[co * 48 + tap];
    }
    if (tid < 64) sb[tid] = b[tid];
    __syncthreads();

    int p = blockIdx.x * 256 + tid;               // 0 .. 32*128*128-1
    int n = p >> 14;
    int rp = p & 16383;
    int ho = rp >> 7, wo = rp & 127;
    int hb = 2 * ho - 1, wb = 2 * wo - 1;
    const float* xb = x + (size_t)n * 3 * 65536;

    float acc[64];
#pragma unroll
    for (int c = 0; c < 64; c++) acc[c] = sb[c];

    for (int ci = 0; ci < 3; ci++) {
        const float* xc = xb + ci * 65536;
        for (int kh = 0; kh < 4; kh++) {
            int hi = hb + kh;
            if ((unsigned)hi >= 256u) continue;
            const float* xr = xc + hi * 256;
            for (int kw = 0; kw < 4; kw++) {
                int wi = wb + kw;
                if ((unsigned)wi >= 256u) continue;
                float v = __ldg(xr + wi);
                const float4* wr = reinterpret_cast<const float4*>(ws[ci * 16 + kh * 4 + kw]);
#pragma unroll
                for (int c4 = 0; c4 < 16; c4++) {
                    float4 wv = wr[c4];
                    acc[c4 * 4 + 0] = fmaf(v, wv.x, acc[c4 * 4 + 0]);
                    acc[c4 * 4 + 1] = fmaf(v, wv.y, acc[c4 * 4 + 1]);
                    acc[c4 * 4 + 2] = fmaf(v, wv.z, acc[c4 * 4 + 2]);
                    acc[c4 * 4 + 3] = fmaf(v, wv.w, acc[c4 * 4 + 3]);
                }
            }
        }
    }
    float* op = out + (size_t)p * 64;
#pragma unroll
    for (int c4 = 0; c4 < 16; c4++) {
        float4 v;
        v.x = fmaxf(acc[c4 * 4 + 0], 0.f);
        v.y = fmaxf(acc[c4 * 4 + 1], 0.f);
        v.z = fmaxf(acc[c4 * 4 + 2], 0.f);
        v.w = fmaxf(acc[c4 * 4 + 3], 0.f);
        reinterpret_cast<float4*>(op)[c4] = v;
    }
}

// ---------------------------------------------------------------------------
// Implicit-GEMM conv (k=4 s=2 p=1) + bias + ReLU.  NHWC in -> NHWC out.
// M = N*HO*WO pixels, N-dim = CO, K = CI*16.
// Block tile 128x128, microtile 8x8 (quadrants of 4), K-chunk 8, prefetch.
// ---------------------------------------------------------------------------
template <int CI, int CO, int HI, int WI>
__global__ __launch_bounds__(256) void conv_igemm(const float* __restrict__ in,
                                                  const float* __restrict__ wT,
                                                  const float* __restrict__ bias,
                                                  float* __restrict__ out) {
    constexpr int HO = HI / 2, WO = WI / 2;
    constexpr int CCH = CI / 8;          // ci chunks per tap
    constexpr int NIT = 16 * CCH;

    __shared__ __align__(16) float As[8][132];
    __shared__ __align__(16) float Bs[8][132];

    int tid = threadIdx.x;
    int rowBase = blockIdx.x * 128;
    int co0 = blockIdx.y * 128;

    // A loader: thread -> (pixel row, 4-float column)
    int arow = tid >> 1, acq = tid & 1;
    int p = rowBase + arow;
    int n = p / (HO * WO);
    int rp = p % (HO * WO);
    int ho = rp / WO, wo = rp % WO;
    int hb = 2 * ho - 1, wb = 2 * wo - 1;
    const float* inb = in + (size_t)n * HI * WI * CI + 4 * acq;

    // B loader: thread -> (k row, 4-float co column)
    int bk = tid >> 5;
    int bc4 = (tid & 31) << 2;
    const float* wb0 = wT + (size_t)bk * CO + co0 + bc4;

    int ty = tid >> 4, tx = tid & 15;

    float acc[2][2][4][4];
#pragma unroll
    for (int a = 0; a < 2; a++)
#pragma unroll
        for (int bq = 0; bq < 2; bq++)
#pragma unroll
            for (int i = 0; i < 4; i++)
#pragma unroll
                for (int j = 0; j < 4; j++) acc[a][bq][i][j] = 0.f;

    float4 aP, bP;
    {   // prefetch iter 0 (tap 0 => kh=0,kw=0)
        int hi = hb, wi = wb;
        aP = make_float4(0.f, 0.f, 0.f, 0.f);
        if ((unsigned)hi < (unsigned)HI && (unsigned)wi < (unsigned)WI)
            aP = *reinterpret_cast<const float4*>(inb + ((size_t)hi * WI + wi) * CI);
        bP = *reinterpret_cast<const float4*>(wb0);
    }

    for (int it = 0; it < NIT; it++) {
        __syncthreads();
        As[4 * acq + 0][arow] = aP.x;
        As[4 * acq + 1][arow] = aP.y;
        As[4 * acq + 2][arow] = aP.z;
        As[4 * acq + 3][arow] = aP.w;
        *reinterpret_cast<float4*>(&Bs[bk][bc4]) = bP;
        __syncthreads();

        if (it + 1 < NIT) {
            int itn = it + 1;
            int t = itn / CCH, ci0 = (itn % CCH) * 8;
            int kh = t >> 2, kw = t & 3;
            int hi = hb + kh, wi = wb + kw;
            aP = make_float4(0.f, 0.f, 0.f, 0.f);
            if ((unsigned)hi < (unsigned)HI && (unsigned)wi < (unsigned)WI)
                aP = *reinterpret_cast<const float4*>(inb + ((size_t)hi * WI + wi) * CI + ci0);
            bP = *reinterpret_cast<const float4*>(wb0 + (size_t)(t * CI + ci0) * CO);
        }

#pragma unroll
        for (int kk = 0; kk < 8; kk++) {
            float4 a0 = *reinterpret_cast<const float4*>(&As[kk][ty * 4]);
            float4 a1 = *reinterpret_cast<const float4*>(&As[kk][64 + ty * 4]);
            float4 b0 = *reinterpret_cast<const float4*>(&Bs[kk][tx * 4]);
            float4 b1 = *reinterpret_cast<const float4*>(&Bs[kk][64 + tx * 4]);
            float av[8] = {a0.x, a0.y, a0.z, a0.w, a1.x, a1.y, a1.z, a1.w};
            float bv[8] = {b0.x, b0.y, b0.z, b0.w, b1.x, b1.y, b1.z, b1.w};
#pragma unroll
            for (int rq = 0; rq < 2; rq++)
#pragma unroll
                for (int i = 0; i < 4; i++)
#pragma unroll
                    for (int cq = 0; cq < 2; cq++)
#pragma unroll
                        for (int j = 0; j < 4; j++)
                            acc[rq][cq][i][j] = fmaf(av[rq * 4 + i], bv[cq * 4 + j], acc[rq][cq][i][j]);
        }
    }

    // epilogue: bias + relu, NHWC store
#pragma unroll
    for (int rq = 0; rq < 2; rq++)
#pragma unroll
        for (int i = 0; i < 4; i++) {
            int r = rowBase + rq * 64 + ty * 4 + i;
            float* op = out + (size_t)r * CO + co0;
#pragma unroll
            for (int cq = 0; cq < 2; cq++) {
                int c = cq * 64 + tx * 4;
                float4 v;
                v.x = fmaxf(acc[rq][cq][i][0] + __ldg(bias + co0 + c + 0), 0.f);
                v.y = fmaxf(acc[rq][cq][i][1] + __ldg(bias + co0 + c + 1), 0.f);
                v.z = fmaxf(acc[rq][cq][i][2] + __ldg(bias + co0 + c + 2), 0.f);
                v.w = fmaxf(acc[rq][cq][i][3] + __ldg(bias + co0 + c + 3), 0.f);
                *reinterpret_cast<float4*>(op + c) = v;
            }
        }
}

// ---------------------------------------------------------------------------
// Codebook row norms + min init
// ---------------------------------------------------------------------------
__global__ void cbnorm_kernel(const float* __restrict__ cb) {
    int code = blockIdx.x * blockDim.x + threadIdx.x;
    const float4* p = reinterpret_cast<const float4*>(cb + (size_t)code * 256);
    float s = 0.f;
#pragma unroll 8
    for (int k = 0; k < 64; k++) {
        float4 v = __ldg(p + k);
        s += v.x * v.x + v.y * v.y + v.z * v.z + v.w * v.w;
    }
    g_cbnorm[code] = s;
}

__global__ void initmin_kernel() {
    int i = blockIdx.x * blockDim.x + threadIdx.x;
    g_min[i] = ~0ULL;
}

// ---------------------------------------------------------------------------
// VQ GEMM + argmin.  S = zf(8192x256) @ cb^T; d = ||c||^2 - 2 S.
// 128x128 tile, 8x8 micro, K-chunk 8, prefetch; packed u64 atomicMin.
// ---------------------------------------------------------------------------
__global__ __launch_bounds__(256) void vq_gemm(const float* __restrict__ zf,
                                               const float* __restrict__ cb) {
    __shared__ __align__(16) float As[8][132];
    __shared__ __align__(16) float Bs[8][132];
    __shared__ unsigned long long smin[128];

    int tid = threadIdx.x;
    int rowBase = blockIdx.y * 128;
    int colBase = blockIdx.x * 128;
    int arow = tid >> 1, acq = tid & 1;
    int ty = tid >> 4, tx = tid & 15;

    if (tid < 128) smin[tid] = ~0ULL;

    const float* za = zf + (size_t)(rowBase + arow) * 256 + 4 * acq;
    const float* ba = cb + (size_t)(colBase + arow) * 256 + 4 * acq;

    float acc[2][2][4][4];
#pragma unroll
    for (int a = 0; a < 2; a++)
#pragma unroll
        for (int bq = 0; bq < 2; bq++)
#pragma unroll
            for (int i = 0; i < 4; i++)
#pragma unroll
                for (int j = 0; j < 4; j++) acc[a][bq][i][j] = 0.f;

    float4 aP = *reinterpret_cast<const float4*>(za);
    float4 bP = __ldg(reinterpret_cast<const float4*>(ba));

    for (int it = 0; it < 32; it++) {
        __syncthreads();
        As[4 * acq + 0][arow] = aP.x;
        As[4 * acq + 1][arow] = aP.y;
        As[4 * acq + 2][arow] = aP.z;
        As[4 * acq + 3][arow] = aP.w;
        Bs[4 * acq + 0][arow] = bP.x;
        Bs[4 * acq + 1][arow] = bP.y;
        Bs[4 * acq + 2][arow] = bP.z;
        Bs[4 * acq + 3][arow] = bP.w;
        __syncthreads();

        if (it + 1 < 32) {
            aP = *reinterpret_cast<const float4*>(za + 8 * (it + 1));
            bP = __ldg(reinterpret_cast<const float4*>(ba + 8 * (it + 1)));
        }

#pragma unroll
        for (int kk = 0; kk < 8; kk++) {
            float4 a0 = *reinterpret_cast<const float4*>(&As[kk][ty * 4]);
            float4 a1 = *reinterpret_cast<const float4*>(&As[kk][64 + ty * 4]);
            float4 b0 = *reinterpret_cast<const float4*>(&Bs[kk][tx * 4]);
            float4 b1 = *reinterpret_cast<const float4*>(&Bs[kk][64 + tx * 4]);
            float av[8] = {a0.x, a0.y, a0.z, a0.w, a1.x, a1.y, a1.z, a1.w};
            float bv[8] = {b0.x, b0.y, b0.z, b0.w, b1.x, b1.y, b1.z, b1.w};
#pragma unroll
            for (int rq = 0; rq < 2; rq++)
#pragma unroll
                for (int i = 0; i < 4; i++)
#pragma unroll
                    for (int cq = 0; cq < 2; cq++)
#pragma unroll
                        for (int j = 0; j < 4; j++)
                            acc[rq][cq][i][j] = fmaf(av[rq * 4 + i], bv[cq * 4 + j], acc[rq][cq][i][j]);
        }
    }

    // distances + per-row argmin
#pragma unroll
    for (int rq = 0; rq < 2; rq++)
#pragma unroll
        for (int i = 0; i < 4; i++) {
            int r = rq * 64 + ty * 4 + i;
            float best = __int_as_float(0x7f800000);
            int bc = 0;
#pragma unroll
            for (int cq = 0; cq < 2; cq++)
#pragma unroll
                for (int j = 0; j < 4; j++) {
                    int col = colBase + cq * 64 + tx * 4 + j;
                    float d = __ldg(&g_cbnorm[col]) - 2.f * acc[rq][cq][i][j];
                    if (d < best) { best = d; bc = col; }
                }
            unsigned ud = __float_as_uint(best);
            ud ^= (ud & 0x80000000u) ? 0xFFFFFFFFu : 0x80000000u;   // monotone key
            unsigned long long key = ((unsigned long long)ud << 32) | (unsigned)bc;
            atomicMin(&smin[r], key);
        }
    __syncthreads();
    if (tid < 128) atomicMin(&g_min[rowBase + tid], smin[tid]);
}

// ---------------------------------------------------------------------------
// Gather codebook rows into z_q (NCHW) + idx
// ---------------------------------------------------------------------------
__global__ void gather_kernel(const float* __restrict__ cb,
                              float* __restrict__ out,
                              int write_zq, int write_idx, long idx_off) {
    int row = blockIdx.x;                 // n*256 + h*16 + w
    int c = threadIdx.x;                  // 0..255
    unsigned idx = (unsigned)(g_min[row] & 0xFFFFFFFFu);
    if (write_zq) {
        float v = __ldg(cb + (size_t)idx * 256 + c);
        int n = row >> 8;
        int p = row & 255;
        out[(size_t)n * 65536 + (size_t)c * 256 + p] = v;
    }
    if (write_idx && c == 0) {
        out[idx_off + row] = (float)idx;
    }
}

// ---------------------------------------------------------------------------
// Launch
// ---------------------------------------------------------------------------
extern "C" void kernel_launch(void* const* d_in, const int* in_sizes, int n_in,
                              void* d_out, int out_size) {
    const float* x  = (const float*)d_in[0];
    const float* w1 = (const float*)d_in[1];
    const float* b1 = (const float*)d_in[2];
    const float* w2 = (const float*)d_in[3];
    const float* b2 = (const float*)d_in[4];
    const float* w3 = (const float*)d_in[5];
    const float* b3 = (const float*)d_in[6];
    const float* w4 = (const float*)d_in[7];
    const float* b4 = (const float*)d_in[8];
    const float* cb = (const float*)d_in[9];
    float* out = (float*)d_out;

    float* a1;  cudaGetSymbolAddress((void**)&a1,  g_a1);
    float* a2;  cudaGetSymbolAddress((void**)&a2,  g_a2);
    float* a3;  cudaGetSymbolAddress((void**)&a3,  g_a3);
    float* zf;  cudaGetSymbolAddress((void**)&zf,  g_zf);
    float* wt2; cudaGetSymbolAddress((void**)&wt2, g_wt2);
    float* wt3; cudaGetSymbolAddress((void**)&wt3, g_wt3);
    float* wt4; cudaGetSymbolAddress((void**)&wt4, g_wt4);

    // weight transposes (tiny)
    wtrans_kernel<<<(16 * 64 * 128 + 255) / 256, 256>>>(w2, wt2, 64, 128);
    wtrans_kernel<<<(16 * 128 * 256 + 255) / 256, 256>>>(w3, wt3, 128, 256);
    wtrans_kernel<<<(16 * 256 * 256 + 255) / 256, 256>>>(w4, wt4, 256, 256);

    // conv chain (NHWC)
    conv1_nhwc<<<2048, 256>>>(x, w1, b1, a1);
    conv_igemm<64, 128, 128, 128><<<dim3(1024, 1), 256>>>(a1, wt2, b2, a2);
    conv_igemm<128, 256, 64, 64><<<dim3(256, 2), 256>>>(a2, wt3, b3, a3);
    conv_igemm<256, 256, 32, 32><<<dim3(64, 2), 256>>>(a3, wt4, b4, zf);

    // VQ
    cbnorm_kernel<<<32, 256>>>(cb);
    initmin_kernel<<<32, 256>>>();
    vq_gemm<<<dim3(64, 64), 256>>>(zf, cb);

    // output layout: [z_q (2,097,152 floats)] [idx (8,192, cast to float)]
    const long ZQ = 2097152;
    int write_zq = 0, write_idx = 0; long idx_off = 0;
    if (out_size >= (int)(ZQ + 8192)) { write_zq = 1; write_idx = 1; idx_off = ZQ; }
    else if (out_size >= (int)ZQ)     { write_zq = 1; }
    else                              { write_idx = 1; idx_off = 0; }

    gather_kernel<<<8192, 256>>>(cb, out, write_zq, write_idx, idx_off);
}

// round 6
// speedup vs baseline: 3.0174x; 1.1124x over previous
#include <cuda_runtime.h>
#include <cstdint>

// ===========================================================================
// Scratch (__device__ globals; no allocation allowed)
// ===========================================================================
__device__ float g_a1[32u * 128u * 128u * 64u];   // conv1 out NHWC
__device__ float g_a2[32u * 64u * 64u * 128u];    // conv2 out NHWC
__device__ float g_a3[32u * 32u * 32u * 256u];    // conv3 out NHWC
__device__ float g_zf[8192u * 256u];              // conv4 out NHWC == zf
__device__ float g_wt2[128u * 1024u];             // w2 as [co][tap*CI+ci]
__device__ float g_wt3[256u * 2048u];
__device__ float g_wt4[256u * 4096u];
__device__ float g_cbnorm[8192];
__device__ unsigned long long g_min[8192];

// ===========================================================================
// mma.sync tf32 helpers (sm_80+ features: valid on plain sm_100 target)
// ===========================================================================
__device__ __forceinline__ void split1(float v, uint32_t& h, uint32_t& l) {
    uint32_t hu;
    asm("cvt.rna.tf32.f32 %0, %1;" : "=r"(hu) : "f"(v));
    float lf = v - __uint_as_float(hu);
    uint32_t lu;
    asm("cvt.rna.tf32.f32 %0, %1;" : "=r"(lu) : "f"(lf));
    h = hu; l = lu;
}

__device__ __forceinline__ void mma8(float* d, const uint32_t* a, const uint32_t* b) {
    asm volatile(
        "mma.sync.aligned.m16n8k8.row.col.f32.tf32.tf32.f32 "
        "{%0,%1,%2,%3}, {%4,%5,%6,%7}, {%8,%9}, {%0,%1,%2,%3};"
        : "+f"(d[0]), "+f"(d[1]), "+f"(d[2]), "+f"(d[3])
        : "r"(a[0]), "r"(a[1]), "r"(a[2]), "r"(a[3]), "r"(b[0]), "r"(b[1]));
}

// Compute one K=32 chunk. As: [s:4][m:8][lane:32][slot:4] fp32; Bs: [s:4][n:16][lane:32][slot:2].
// Warp (wm,wn) computes 64x32: m-blocks wm*4+i, n-blocks wn*4+j.
__device__ __forceinline__ void compute_chunk(const float* As, const float* Bs,
                                              int wm, int wn, int lane,
                                              float acc[4][4][4]) {
#pragma unroll
    for (int s = 0; s < 4; s++) {
        uint32_t ah[4][4], al[4][4], bh[4][2], bl[4][2];
#pragma unroll
        for (int i = 0; i < 4; i++) {
            float4 v = *reinterpret_cast<const float4*>(As + (((s * 8) + wm * 4 + i) * 32 + lane) * 4);
            split1(v.x, ah[i][0], al[i][0]);
            split1(v.y, ah[i][1], al[i][1]);
            split1(v.z, ah[i][2], al[i][2]);
            split1(v.w, ah[i][3], al[i][3]);
        }
#pragma unroll
        for (int j = 0; j < 4; j++) {
            float2 v = *reinterpret_cast<const float2*>(Bs + (((s * 16) + wn * 4 + j) * 32 + lane) * 2);
            split1(v.x, bh[j][0], bl[j][0]);
            split1(v.y, bh[j][1], bl[j][1]);
        }
#pragma unroll
        for (int i = 0; i < 4; i++)
#pragma unroll
            for (int j = 0; j < 4; j++) {
                mma8(acc[i][j], ah[i], bh[j]);
                mma8(acc[i][j], al[i], bh[j]);
                mma8(acc[i][j], ah[i], bl[j]);
            }
    }
}

// ===========================================================================
// Weight transpose: w[co][ci][kh][kw] -> wT[co][ (kh*4+kw)*CI + ci ]
// ===========================================================================
__global__ void wtrans_kernel(const float* __restrict__ w, float* __restrict__ wT,
                              int CI, int CO) {
    int id = blockIdx.x * 256 + threadIdx.x;
    int K = CI * 16;
    if (id >= CO * K) return;
    int co = id / K;
    int r = id % K;
    int tap = r / CI;
    int ci = r % CI;
    wT[id] = w[(co * CI + ci) * 16 + tap];
}

// ===========================================================================
// Conv1: CI=3, k=4 s=2 p=1 + bias + ReLU. NCHW in -> NHWC out.
// ===========================================================================
__global__ __launch_bounds__(256) void conv1_nhwc(const float* __restrict__ x,
                                                  const float* __restrict__ w,
                                                  const float* __restrict__ b,
                                                  float* __restrict__ out) {
    __shared__ __align__(16) float ws[48][64];
    __shared__ float sb[64];
    int tid = threadIdx.x;
    for (int i = tid; i < 3072; i += 256) {
        int tap = i >> 6, co = i & 63;
        ws[tap][co] = w[co * 48 + tap];
    }
    if (tid < 64) sb[tid] = b[tid];
    __syncthreads();

    int p = blockIdx.x * 128 + (tid >> 1);
    int half = tid & 1;
    int n = p >> 14;
    int rp = p & 16383;
    int ho = rp >> 7, wo = rp & 127;
    int hb = 2 * ho - 1, wb = 2 * wo - 1;
    const float* xb = x + (size_t)n * 3 * 65536;

    float acc[32];
#pragma unroll
    for (int c = 0; c < 32; c++) acc[c] = sb[half * 32 + c];

    for (int ci = 0; ci < 3; ci++) {
        const float* xc = xb + ci * 65536;
        for (int kh = 0; kh < 4; kh++) {
            int hi = hb + kh;
            if ((unsigned)hi >= 256u) continue;
            const float* xr = xc + hi * 256;
            for (int kw = 0; kw < 4; kw++) {
                int wi = wb + kw;
                if ((unsigned)wi >= 256u) continue;
                float v = __ldg(xr + wi);
                const float4* wr = reinterpret_cast<const float4*>(&ws[ci * 16 + kh * 4 + kw][half * 32]);
#pragma unroll
                for (int c4 = 0; c4 < 8; c4++) {
                    float4 wv = wr[c4];
                    acc[c4 * 4 + 0] = fmaf(v, wv.x, acc[c4 * 4 + 0]);
                    acc[c4 * 4 + 1] = fmaf(v, wv.y, acc[c4 * 4 + 1]);
                    acc[c4 * 4 + 2] = fmaf(v, wv.z, acc[c4 * 4 + 2]);
                    acc[c4 * 4 + 3] = fmaf(v, wv.w, acc[c4 * 4 + 3]);
                }
            }
        }
    }
    float* op = out + (size_t)p * 64 + half * 32;
#pragma unroll
    for (int c4 = 0; c4 < 8; c4++) {
        float4 v;
        v.x = fmaxf(acc[c4 * 4 + 0], 0.f);
        v.y = fmaxf(acc[c4 * 4 + 1], 0.f);
        v.z = fmaxf(acc[c4 * 4 + 2], 0.f);
        v.w = fmaxf(acc[c4 * 4 + 3], 0.f);
        reinterpret_cast<float4*>(op)[c4] = v;
    }
}

// ===========================================================================
// Tensor-core implicit-GEMM conv (k=4 s=2 p=1) + bias + ReLU, NHWC->NHWC.
// Block 128x128, K = CI*16 chunked by 32, 3xTF32 via mma.sync. 256 threads.
// Dynamic smem: aux[128] + 2 x (A 4096 + B 4096) floats = 66048 B.
// ===========================================================================
template <int CI, int CO, int HI, int WI>
__global__ __launch_bounds__(256) void conv_mma(const float* __restrict__ in,
                                                const float* __restrict__ wT,
                                                const float* __restrict__ bias,
                                                float* __restrict__ out) {
    constexpr int HO = HI / 2, WO = WI / 2;
    constexpr int K = CI * 16;
    constexpr int NCH = K / 32;
    extern __shared__ __align__(16) float smem[];
    float* aux = smem;

    int tid = threadIdx.x, lane = tid & 31, m = tid >> 5;   // m = warp id = fill m-block
    int wm = m >> 2, wn = m & 3;
    int rowBase = blockIdx.x * 128;
    int co0 = blockIdx.y * 128;

    if (tid < 128) aux[tid] = bias[co0 + tid];

    // --- A fill metadata: this thread's 2 pixel rows ---
    int rA0 = rowBase + m * 16 + (lane >> 2);
    int rA1 = rA0 + 8;
    int n0 = rA0 / (HO * WO), rp0 = rA0 % (HO * WO);
    int n1 = rA1 / (HO * WO), rp1 = rA1 % (HO * WO);
    int hb0 = 2 * (rp0 / WO) - 1, wb0 = 2 * (rp0 % WO) - 1;
    int hb1 = 2 * (rp1 / WO) - 1, wb1 = 2 * (rp1 % WO) - 1;
    size_t ab0 = (size_t)n0 * HI * WI * CI;
    size_t ab1 = (size_t)n1 * HI * WI * CI;

    // --- B fill metadata: 2 weight rows ---
    size_t wro0 = (size_t)(co0 + (0 * 8 + m) * 8 + (lane >> 2)) * K + (lane & 3);
    size_t wro1 = (size_t)(co0 + (1 * 8 + m) * 8 + (lane >> 2)) * K + (lane & 3);

    float pa[16], pb[16];
    auto loadA = [&](int kk) {
        int kk32 = kk * 32;
        int tap = kk32 / CI, ci0 = kk32 % CI;
        int kh = tap >> 2, kw = tap & 3;
        int hi0 = hb0 + kh, wi0 = wb0 + kw;
        int hi1 = hb1 + kh, wi1 = wb1 + kw;
        bool ok0 = (unsigned)hi0 < (unsigned)HI && (unsigned)wi0 < (unsigned)WI;
        bool ok1 = (unsigned)hi1 < (unsigned)HI && (unsigned)wi1 < (unsigned)WI;
        const float* p0 = in + ab0 + ((size_t)hi0 * WI + wi0) * CI + ci0 + (lane & 3);
        const float* p1 = in + ab1 + ((size_t)hi1 * WI + wi1) * CI + ci0 + (lane & 3);
#pragma unroll
        for (int s = 0; s < 4; s++) {
            pa[s * 4 + 0] = ok0 ? __ldg(p0 + s * 8) : 0.f;
            pa[s * 4 + 1] = ok1 ? __ldg(p1 + s * 8) : 0.f;
            pa[s * 4 + 2] = ok0 ? __ldg(p0 + s * 8 + 4) : 0.f;
            pa[s * 4 + 3] = ok1 ? __ldg(p1 + s * 8 + 4) : 0.f;
        }
    };
    auto loadB = [&](int kk) {
#pragma unroll
        for (int s = 0; s < 4; s++) {
            pb[0 + s * 2 + 0] = __ldg(wT + wro0 + kk * 32 + s * 8);
            pb[0 + s * 2 + 1] = __ldg(wT + wro0 + kk * 32 + s * 8 + 4);
            pb[8 + s * 2 + 0] = __ldg(wT + wro1 + kk * 32 + s * 8);
            pb[8 + s * 2 + 1] = __ldg(wT + wro1 + kk * 32 + s * 8 + 4);
        }
    };
    auto stsAB = [&](int buf) {
        float* As = smem + 128 + buf * 8192;
        float* Bs = As + 4096;
#pragma unroll
        for (int s = 0; s < 4; s++)
            *reinterpret_cast<float4*>(As + ((s * 8 + m) * 32 + lane) * 4) =
                make_float4(pa[s * 4 + 0], pa[s * 4 + 1], pa[s * 4 + 2], pa[s * 4 + 3]);
#pragma unroll
        for (int q = 0; q < 2; q++)
#pragma unroll
            for (int s = 0; s < 4; s++)
                *reinterpret_cast<float2*>(Bs + ((s * 16 + q * 8 + m) * 32 + lane) * 2) =
                    make_float2(pb[q * 8 + s * 2 + 0], pb[q * 8 + s * 2 + 1]);
    };

    float acc[4][4][4];
#pragma unroll
    for (int i = 0; i < 4; i++)
#pragma unroll
        for (int j = 0; j < 4; j++)
#pragma unroll
            for (int e = 0; e < 4; e++) acc[i][j][e] = 0.f;

    loadA(0); loadB(0);
    stsAB(0);
    __syncthreads();

    for (int kk = 0; kk < NCH; kk++) {
        if (kk + 1 < NCH) { loadA(kk + 1); loadB(kk + 1); }
        const float* As = smem + 128 + (kk & 1) * 8192;
        compute_chunk(As, As + 4096, wm, wn, lane, acc);
        if (kk + 1 < NCH) stsAB((kk + 1) & 1);
        __syncthreads();
    }

    // epilogue: bias + relu, NHWC store (float2 per fragment row)
#pragma unroll
    for (int i = 0; i < 4; i++) {
        int rlo = rowBase + (wm * 4 + i) * 16 + (lane >> 2);
        int rhi = rlo + 8;
#pragma unroll
        for (int j = 0; j < 4; j++) {
            int c = (wn * 4 + j) * 8 + 2 * (lane & 3);
            float b0 = aux[c], b1 = aux[c + 1];
            float2 v0 = make_float2(fmaxf(acc[i][j][0] + b0, 0.f), fmaxf(acc[i][j][1] + b1, 0.f));
            float2 v1 = make_float2(fmaxf(acc[i][j][2] + b0, 0.f), fmaxf(acc[i][j][3] + b1, 0.f));
            *reinterpret_cast<float2*>(out + (size_t)rlo * CO + co0 + c) = v0;
            *reinterpret_cast<float2*>(out + (size_t)rhi * CO + co0 + c) = v1;
        }
    }
}

// ===========================================================================
// Tensor-core VQ: S = zf(8192x256) @ cb^T; d = ||c||^2 - 2S; row argmin.
// ===========================================================================
__global__ __launch_bounds__(256) void vq_mma(const float* __restrict__ zf,
                                              const float* __restrict__ cb) {
    constexpr int NCH = 8;   // K = 256
    extern __shared__ __align__(16) float smem[];
    float* aux = smem;
    __shared__ unsigned long long smin[128];

    int tid = threadIdx.x, lane = tid & 31, m = tid >> 5;
    int wm = m >> 2, wn = m & 3;
    int colBase = blockIdx.x * 128;
    int rowBase = blockIdx.y * 128;

    if (tid < 128) { aux[tid] = g_cbnorm[colBase + tid]; smin[tid] = ~0ULL; }

    const float* pA0 = zf + (size_t)(rowBase + m * 16 + (lane >> 2)) * 256 + (lane & 3);
    const float* pA1 = pA0 + 8 * 256;
    const float* pB0 = cb + (size_t)(colBase + (0 * 8 + m) * 8 + (lane >> 2)) * 256 + (lane & 3);
    const float* pB1 = cb + (size_t)(colBase + (1 * 8 + m) * 8 + (lane >> 2)) * 256 + (lane & 3);

    float pa[16], pb[16];
    auto loadAB = [&](int kk) {
#pragma unroll
        for (int s = 0; s < 4; s++) {
            pa[s * 4 + 0] = __ldg(pA0 + kk * 32 + s * 8);
            pa[s * 4 + 1] = __ldg(pA1 + kk * 32 + s * 8);
            pa[s * 4 + 2] = __ldg(pA0 + kk * 32 + s * 8 + 4);
            pa[s * 4 + 3] = __ldg(pA1 + kk * 32 + s * 8 + 4);
            pb[0 + s * 2 + 0] = __ldg(pB0 + kk * 32 + s * 8);
            pb[0 + s * 2 + 1] = __ldg(pB0 + kk * 32 + s * 8 + 4);
            pb[8 + s * 2 + 0] = __ldg(pB1 + kk * 32 + s * 8);
            pb[8 + s * 2 + 1] = __ldg(pB1 + kk * 32 + s * 8 + 4);
        }
    };
    auto stsAB = [&](int buf) {
        float* As = smem + 128 + buf * 8192;
        float* Bs = As + 4096;
#pragma unroll
        for (int s = 0; s < 4; s++)
            *reinterpret_cast<float4*>(As + ((s * 8 + m) * 32 + lane) * 4) =
                make_float4(pa[s * 4 + 0], pa[s * 4 + 1], pa[s * 4 + 2], pa[s * 4 + 3]);
#pragma unroll
        for (int q = 0; q < 2; q++)
#pragma unroll
            for (int s = 0; s < 4; s++)
                *reinterpret_cast<float2*>(Bs + ((s * 16 + q * 8 + m) * 32 + lane) * 2) =
                    make_float2(pb[q * 8 + s * 2 + 0], pb[q * 8 + s * 2 + 1]);
    };

    float acc[4][4][4];
#pragma unroll
    for (int i = 0; i < 4; i++)
#pragma unroll
        for (int j = 0; j < 4; j++)
#pragma unroll
            for (int e = 0; e < 4; e++) acc[i][j][e] = 0.f;

    loadAB(0);
    stsAB(0);
    __syncthreads();

    for (int kk = 0; kk < NCH; kk++) {
        if (kk + 1 < NCH) loadAB(kk + 1);
        const float* As = smem + 128 + (kk & 1) * 8192;
        compute_chunk(As, As + 4096, wm, wn, lane, acc);
        if (kk + 1 < NCH) stsAB((kk + 1) & 1);
        __syncthreads();
    }

    // argmin epilogue
#pragma unroll
    for (int i = 0; i < 4; i++) {
        int rlo = (wm * 4 + i) * 16 + (lane >> 2);
        float bestl = __int_as_float(0x7f800000); int bcl = 0;
        float besth = __int_as_float(0x7f800000); int bch = 0;
#pragma unroll
        for (int j = 0; j < 4; j++) {
            int c = (wn * 4 + j) * 8 + 2 * (lane & 3);
            float n0 = aux[c], n1 = aux[c + 1];
            float d0 = n0 - 2.f * acc[i][j][0];
            float d1 = n1 - 2.f * acc[i][j][1];
            float d2 = n0 - 2.f * acc[i][j][2];
            float d3 = n1 - 2.f * acc[i][j][3];
            if (d0 < bestl) { bestl = d0; bcl = c; }
            if (d1 < bestl) { bestl = d1; bcl = c + 1; }
            if (d2 < besth) { besth = d2; bch = c; }
            if (d3 < besth) { besth = d3; bch = c + 1; }
        }
        unsigned ul = __float_as_uint(bestl);
        ul ^= (ul & 0x80000000u) ? 0xFFFFFFFFu : 0x80000000u;
        unsigned uh = __float_as_uint(besth);
        uh ^= (uh & 0x80000000u) ? 0xFFFFFFFFu : 0x80000000u;
        atomicMin(&smin[rlo], ((unsigned long long)ul << 32) | (unsigned)(colBase + bcl));
        atomicMin(&smin[rlo + 8], ((unsigned long long)uh << 32) | (unsigned)(colBase + bch));
    }
    __syncthreads();
    if (tid < 128) atomicMin(&g_min[rowBase + tid], smin[tid]);
}

// ===========================================================================
// cbnorm / initmin / gather
// ===========================================================================
__global__ void cbnorm_kernel(const float* __restrict__ cb) {
    int code = blockIdx.x * blockDim.x + threadIdx.x;
    const float4* p = reinterpret_cast<const float4*>(cb + (size_t)code * 256);
    float s = 0.f;
#pragma unroll 8
    for (int k = 0; k < 64; k++) {
        float4 v = __ldg(p + k);
        s += v.x * v.x + v.y * v.y + v.z * v.z + v.w * v.w;
    }
    g_cbnorm[code] = s;
}

__global__ void initmin_kernel() {
    int i = blockIdx.x * blockDim.x + threadIdx.x;
    g_min[i] = ~0ULL;
}

__global__ void gather_kernel(const float* __restrict__ cb,
                              float* __restrict__ out,
                              int write_zq, int write_idx, long idx_off) {
    int row = blockIdx.x;
    int c = threadIdx.x;
    unsigned idx = (unsigned)(g_min[row] & 0xFFFFFFFFu);
    if (write_zq) {
        float v = __ldg(cb + (size_t)idx * 256 + c);
        int n = row >> 8;
        int p = row & 255;
        out[(size_t)n * 65536 + (size_t)c * 256 + p] = v;
    }
    if (write_idx && c == 0) out[idx_off + row] = (float)idx;
}

// ===========================================================================
// Launch
// ===========================================================================
static constexpr int GEMM_SMEM = (128 + 2 * 8192) * 4;   // 66048 bytes

extern "C" void kernel_launch(void* const* d_in, const int* in_sizes, int n_in,
                              void* d_out, int out_size) {
    const float* x  = (const float*)d_in[0];
    const float* w1 = (const float*)d_in[1];
    const float* b1 = (const float*)d_in[2];
    const float* w2 = (const float*)d_in[3];
    const float* b2 = (const float*)d_in[4];
    const float* w3 = (const float*)d_in[5];
    const float* b3 = (const float*)d_in[6];
    const float* w4 = (const float*)d_in[7];
    const float* b4 = (const float*)d_in[8];
    const float* cb = (const float*)d_in[9];
    float* out = (float*)d_out;

    float* a1;  cudaGetSymbolAddress((void**)&a1,  g_a1);
    float* a2;  cudaGetSymbolAddress((void**)&a2,  g_a2);
    float* a3;  cudaGetSymbolAddress((void**)&a3,  g_a3);
    float* zf;  cudaGetSymbolAddress((void**)&zf,  g_zf);
    float* wt2; cudaGetSymbolAddress((void**)&wt2, g_wt2);
    float* wt3; cudaGetSymbolAddress((void**)&wt3, g_wt3);
    float* wt4; cudaGetSymbolAddress((void**)&wt4, g_wt4);

    static int attr_done = 0;
    if (!attr_done) {
        cudaFuncSetAttribute(conv_mma<64, 128, 128, 128>, cudaFuncAttributeMaxDynamicSharedMemorySize, GEMM_SMEM);
        cudaFuncSetAttribute(conv_mma<128, 256, 64, 64>, cudaFuncAttributeMaxDynamicSharedMemorySize, GEMM_SMEM);
        cudaFuncSetAttribute(conv_mma<256, 256, 32, 32>, cudaFuncAttributeMaxDynamicSharedMemorySize, GEMM_SMEM);
        cudaFuncSetAttribute(vq_mma, cudaFuncAttributeMaxDynamicSharedMemorySize, GEMM_SMEM);
        attr_done = 1;
    }

    // weight transposes (tiny)
    wtrans_kernel<<<(128 * 1024 + 255) / 256, 256>>>(w2, wt2, 64, 128);
    wtrans_kernel<<<(256 * 2048 + 255) / 256, 256>>>(w3, wt3, 128, 256);
    wtrans_kernel<<<(256 * 4096 + 255) / 256, 256>>>(w4, wt4, 256, 256);
    cbnorm_kernel<<<32, 256>>>(cb);
    initmin_kernel<<<32, 256>>>();

    // conv chain (NHWC)
    conv1_nhwc<<<4096, 256>>>(x, w1, b1, a1);
    conv_mma<64, 128, 128, 128><<<dim3(1024, 1), 256, GEMM_SMEM>>>(a1, wt2, b2, a2);
    conv_mma<128, 256, 64, 64><<<dim3(256, 2), 256, GEMM_SMEM>>>(a2, wt3, b3, a3);
    conv_mma<256, 256, 32, 32><<<dim3(64, 2), 256, GEMM_SMEM>>>(a3, wt4, b4, zf);

    // VQ
    vq_mma<<<dim3(64, 64), 256, GEMM_SMEM>>>(zf, cb);

    // output: [z_q (2,097,152 floats)] [idx (8,192, cast to float)]
    const long ZQ = 2097152;
    int write_zq = 0, write_idx = 0; long idx_off = 0;
    if (out_size >= (int)(ZQ + 8192)) { write_zq = 1; write_idx = 1; idx_off = ZQ; }
    else if (out_size >= (int)ZQ)     { write_zq = 1; }
    else                              { write_idx = 1; idx_off = 0; }

    gather_kernel<<<8192, 256>>>(cb, out, write_zq, write_idx, idx_off);
}